// round 6
// baseline (speedup 1.0000x reference)
#include <cuda_runtime.h>
#include <cuda_bf16.h>
#include <math.h>

#define Hh 256
#define Ss 64
#define ANa 16
#define Dd 8
#define Tt 32
#define Nn 64
#define NVv 32
#define HGg 770   // 2 + 3*H
#define G3 2310   // 3*HG
#define ROW 338   // 1+AN+1+H+S

// ---------------- scratch (device globals; no allocation allowed) ----------------
__device__ float g_GIv[NVv * G3];            // per-vocab input gates (incl b_ih)
__device__ float g_GH[4 * Nn * G3];          // split-K partials of h@Whh^T
__device__ float g_X[Ss * Nn * HGg];         // GRU outputs  [s][n][770]
__device__ float g_W0t[2048 * 256];          // conv0_w transposed: [o*8+d][h]
__device__ float g_linT[256 * 16384];        // lin_w re-laid: [o][p*256+c]
__device__ float g_psiT[16 * 256 * 256];     // psi_w re-laid: [a][h][o]
__device__ float g_p[Nn * Ss];
__device__ float g_ps[Nn * Ss];
__device__ float g_nMp[Nn * Ss];
__device__ float g_nMm[Nn * Ss];
__device__ float g_r[Nn * 256];
__device__ float g_G[4 * Nn * 2048];         // split-K partials of G
__device__ float g_x0[4096 * 256];           // NHWC activations
__device__ float g_x1[4096 * 256];
__device__ float g_s[Nn * 256];
__device__ float g_lp[32 * Nn * 256];        // lin split-K partials

// ---------------- generic NT SGEMM: C = A(MxK) . B(NxK)^T, optional splitK ----------------
template<int TM, int TN, int TK>
__global__ void gemm_nt(const float* __restrict__ A, int lda,
                        const float* __restrict__ B, int ldb,
                        float* __restrict__ C,
                        int M, int N, int K,
                        const float* __restrict__ bias, int relu)
{
    const int NT = (TM / 4) * (TN / 4);
    __shared__ float As[TK][TM + 1];
    __shared__ float Bs[TK][TN + 1];
    int m0 = blockIdx.x * TM;
    int n0 = blockIdx.y * TN;
    int ksplit = gridDim.z;
    int kz = blockIdx.z;
    int kc = (K + ksplit - 1) / ksplit;
    int k_begin = kz * kc;
    int k_end = min(K, k_begin + kc);
    int tid = threadIdx.x;
    int ty = tid / (TN / 4);
    int tx = tid % (TN / 4);
    float acc[4][4];
    #pragma unroll
    for (int i = 0; i < 4; i++)
        #pragma unroll
        for (int j = 0; j < 4; j++) acc[i][j] = 0.f;

    for (int k0 = k_begin; k0 < k_end; k0 += TK) {
        for (int e = tid; e < TM * TK; e += NT) {
            int mm = e / TK, kk = e % TK;
            int gm = m0 + mm, gk = k0 + kk;
            As[kk][mm] = (gm < M && gk < k_end) ? A[(size_t)gm * lda + gk] : 0.f;
        }
        for (int e = tid; e < TN * TK; e += NT) {
            int nn = e / TK, kk = e % TK;
            int gn = n0 + nn, gk = k0 + kk;
            Bs[kk][nn] = (gn < N && gk < k_end) ? B[(size_t)gn * ldb + gk] : 0.f;
        }
        __syncthreads();
        #pragma unroll
        for (int kk = 0; kk < TK; kk++) {
            float a[4], b[4];
            #pragma unroll
            for (int i = 0; i < 4; i++) a[i] = As[kk][ty * 4 + i];
            #pragma unroll
            for (int j = 0; j < 4; j++) b[j] = Bs[kk][tx * 4 + j];
            #pragma unroll
            for (int i = 0; i < 4; i++)
                #pragma unroll
                for (int j = 0; j < 4; j++) acc[i][j] += a[i] * b[j];
        }
        __syncthreads();
    }
    float* Cz = C + (size_t)kz * M * N;
    #pragma unroll
    for (int i = 0; i < 4; i++) {
        int gm = m0 + ty * 4 + i;
        if (gm >= M) continue;
        #pragma unroll
        for (int j = 0; j < 4; j++) {
            int gn = n0 + tx * 4 + j;
            if (gn >= N) continue;
            float v = acc[i][j];
            if (ksplit == 1) {
                if (bias) v += bias[gn];
                if (relu) v = fmaxf(v, 0.f);
            }
            Cz[(size_t)gm * N + gn] = v;
        }
    }
}

// ---------------- weight re-layouts (once per call; cheap) ----------------
__global__ void transpose_w0(const float* __restrict__ w, float* __restrict__ wt)
{
    int idx = blockIdx.x * 256 + threadIdx.x;          // 2048*256
    if (idx >= 2048 * 256) return;
    int h = idx & 255, j = idx >> 8;
    int o = j >> 3, d = j & 7;
    wt[idx] = w[o * 2048 + h * 8 + d];
}
__global__ void transpose_lin(const float* __restrict__ w, float* __restrict__ wt)
{
    int idx = blockIdx.x * 256 + threadIdx.x;          // 256*16384
    if (idx >= 256 * 16384) return;
    int c = idx & 255;
    int p = (idx >> 8) & 63;
    int o = idx >> 14;
    wt[idx] = w[(size_t)o * 16384 + c * 64 + p];
}
__global__ void transpose_psi(const float* __restrict__ w, float* __restrict__ wt)
{
    int idx = blockIdx.x * 256 + threadIdx.x;          // 16*256*256
    if (idx >= 16 * 256 * 256) return;
    int o = idx & 255;
    int h = (idx >> 8) & 255;
    int a = idx >> 16;
    wt[idx] = w[(size_t)o * 4096 + h * 16 + a];
}

// ---------------- GRU gate (fuses split-K reduce + gates + gi gather) ----------------
__global__ void gru_gate(const float* __restrict__ GIv, const float* __restrict__ GH,
                         const float* __restrict__ b_hh, const int* __restrict__ subtasks,
                         float* __restrict__ X, int s)
{
    int idx = blockIdx.x * 256 + threadIdx.x;
    if (idx >= Nn * HGg) return;
    int n = idx / HGg, j = idx % HGg;
    int v = subtasks[n * Ss + s];
    const float* gi = GIv + v * G3;
    float gir = gi[j], giz = gi[HGg + j], gin = gi[2 * HGg + j];
    float ghr = b_hh[j], ghz = b_hh[HGg + j], ghn = b_hh[2 * HGg + j];
    float hprev = 0.f;
    if (s > 0) {
        const float* gh = GH + n * G3;
        #pragma unroll
        for (int ks = 0; ks < 4; ks++) {
            const float* g = gh + (size_t)ks * Nn * G3;
            ghr += g[j]; ghz += g[HGg + j]; ghn += g[2 * HGg + j];
        }
        hprev = X[(size_t)((s - 1) * Nn + n) * HGg + j];
    }
    float r = 1.f / (1.f + expf(-(gir + ghr)));
    float z = 1.f / (1.f + expf(-(giz + ghz)));
    float nn = tanhf(gin + r * ghn);
    X[(size_t)(s * Nn + n) * HGg + j] = (1.f - z) * nn + z * hprev;
}

// ---------------- loop-invariant norms of Mp/Mm rows ----------------
__global__ void norms_kernel(const float* __restrict__ X, float* __restrict__ nMp, float* __restrict__ nMm)
{
    int b = blockIdx.x;                 // b = n*64 + s
    int n = b >> 6, sp = b & 63;
    const float* row = X + (size_t)(sp * Nn + n) * HGg;
    __shared__ float rp[128], rm[128];
    int tid = threadIdx.x;              // 128
    float ap = 0.f, am = 0.f;
    for (int h = tid; h < 256; h += 128) {
        float x = row[2 + 2 * Hh + h]; ap += x * x;
        float y = row[2 + Hh + h];     am += y * y;
    }
    rp[tid] = ap; rm[tid] = am;
    __syncthreads();
    for (int off = 64; off > 0; off >>= 1) {
        if (tid < off) { rp[tid] += rp[tid + off]; rm[tid] += rm[tid + off]; }
        __syncthreads();
    }
    if (tid == 0) { nMp[b] = sqrtf(rp[0]); nMm[b] = sqrtf(rm[0]); }
}

// ---------------- p_init ----------------
__global__ void p_init_kernel(const float* __restrict__ hxs, const float* __restrict__ X, float* __restrict__ p)
{
    int n = blockIdx.x;
    __shared__ int anynz;
    if (threadIdx.x == 0) anynz = 0;
    __syncthreads();
    for (int i = threadIdx.x; i < ROW; i += blockDim.x)
        if (hxs[n * ROW + i] != 0.f) atomicOr(&anynz, 1);
    __syncthreads();
    bool newep = (anynz == 0);
    for (int sp = threadIdx.x; sp < Ss; sp += blockDim.x) {
        float p0 = X[(size_t)(sp * Nn + n) * HGg + 1];
        p[n * Ss + sp] = newep ? p0 : hxs[n * ROW + 1 + ANa + 1 + Hh + sp];
    }
}

// ---------------- step A: softmax(p) and r = ps @ M ----------------
__global__ void step_a(const float* __restrict__ p, float* __restrict__ ps_out,
                       float* __restrict__ r_out, const float* __restrict__ X)
{
    int n = blockIdx.x;
    __shared__ float ps[64];
    __shared__ float tmp[64];
    int tid = threadIdx.x;              // 256
    if (tid < 64) tmp[tid] = p[n * 64 + tid];
    __syncthreads();
    if (tid == 0) {
        float m = tmp[0];
        for (int i = 1; i < 64; i++) m = fmaxf(m, tmp[i]);
        float sum = 0.f;
        for (int i = 0; i < 64; i++) { float e = expf(tmp[i] - m); ps[i] = e; sum += e; }
        float inv = 1.f / sum;
        for (int i = 0; i < 64; i++) ps[i] *= inv;
    }
    __syncthreads();
    if (tid < 64) ps_out[n * 64 + tid] = ps[tid];
    float acc = 0.f;
    for (int s = 0; s < 64; s++)
        acc += ps[s] * X[(size_t)(s * Nn + n) * HGg + 2 + tid];
    r_out[n * 256 + tid] = acc;
}

// ---------------- step C: s0[n,p,o] = relu(b0[o] + sum_d G[n,o,d]*base[n,d,p]) ----------------
__global__ void step_c(const float* __restrict__ Gpart, const float* __restrict__ base_t,
                       const float* __restrict__ b0, float* __restrict__ out)
{
    int n = blockIdx.x;
    int o0 = blockIdx.y * 64;
    __shared__ float bs[8 * 64];        // [d][p]
    __shared__ float Gs[64 * 8];        // [o_l][d]
    int tid = threadIdx.x;              // 256
    for (int e = tid; e < 512; e += 256) bs[e] = base_t[n * 512 + e];
    for (int e = tid; e < 512; e += 256) {
        int j = o0 * 8 + e;
        float v = 0.f;
        #pragma unroll
        for (int ks = 0; ks < 4; ks++) v += Gpart[(size_t)ks * Nn * 2048 + n * 2048 + j];
        Gs[e] = v;
    }
    __syncthreads();
    int o_l = tid & 63;
    int pg = tid >> 6;
    float bias = b0[o0 + o_l];
    for (int k = 0; k < 16; k++) {
        int pp = pg * 16 + k;
        float acc = bias;
        #pragma unroll
        for (int d = 0; d < 8; d++) acc += Gs[o_l * 8 + d] * bs[d * 64 + pp];
        out[((size_t)n * 64 + pp) * 256 + o0 + o_l] = fmaxf(acc, 0.f);
    }
}

// ---------------- lin split-K reduce + bias + relu ----------------
__global__ void lin_reduce(const float* __restrict__ part, const float* __restrict__ bias,
                           float* __restrict__ s_out)
{
    int idx = blockIdx.x * 256 + threadIdx.x;    // 64*256
    int o = idx & 255;
    float v = bias[o];
    for (int ks = 0; ks < 32; ks++) v += part[(size_t)ks * Nn * 256 + idx];
    s_out[idx] = fmaxf(v, 0.f);
}

// ---------------- step head: actor/critic/psi/cos/p update + output row ----------------
__global__ void step_head(
    const float* __restrict__ s_buf, const float* __restrict__ ps_buf,
    const float* __restrict__ X, const float* __restrict__ nMp, const float* __restrict__ nMm,
    const float* __restrict__ psiT, const float* __restrict__ psi_b,
    const float* __restrict__ actor_w, const float* __restrict__ actor_b,
    const float* __restrict__ critic_w, const float* __restrict__ critic_b,
    const float* __restrict__ inter_t, const int* __restrict__ act_t,
    float* __restrict__ p_buf, float* __restrict__ out_t)
{
    int n = blockIdx.x;
    int tid = threadIdx.x;              // 256
    __shared__ float s_sm[256];
    __shared__ float e_sm[256];
    __shared__ float red[256];
    __shared__ float logit_sm[16];
    __shared__ float probs_sm[16];
    __shared__ float v_sm;
    __shared__ float enorm_sm;
    s_sm[tid] = s_buf[n * 256 + tid];
    __syncthreads();
    int a = act_t[n];
    // e = psi(s, a)
    {
        float acc = psi_b[tid];
        const float* P = psiT + (size_t)a * 256 * 256;
        for (int h = 0; h < 256; h++) acc += P[h * 256 + tid] * s_sm[h];
        e_sm[tid] = acc;
        red[tid] = acc * acc;
    }
    __syncthreads();
    for (int off = 128; off > 0; off >>= 1) {
        if (tid < off) red[tid] += red[tid + off];
        __syncthreads();
    }
    if (tid == 0) enorm_sm = sqrtf(red[0]);
    // logits + critic
    if (tid < 16) {
        float acc = actor_b[tid];
        for (int h = 0; h < 256; h++) acc += actor_w[tid * 256 + h] * s_sm[h];
        logit_sm[tid] = acc;
    } else if (tid == 32) {
        float acc = critic_b[0];
        for (int h = 0; h < 256; h++) acc += critic_w[h] * s_sm[h];
        v_sm = acc;
    }
    __syncthreads();
    if (tid == 0) {
        float pr[16], nonzero[16];
        float mx = logit_sm[0];
        for (int aa = 1; aa < 16; aa++) mx = fmaxf(mx, logit_sm[aa]);
        float sum = 0.f;
        for (int aa = 0; aa < 16; aa++) { pr[aa] = expf(logit_sm[aa] - mx); sum += pr[aa]; }
        float inv = 1.f / sum;
        float nzsum = 0.f;
        for (int aa = 0; aa < 16; aa++) {
            float nz = (aa < 5) ? 1.f : inter_t[n * 11 + aa - 5];
            nonzero[aa] = nz; nzsum += fabsf(nz);
        }
        float psum = 0.f;
        for (int aa = 0; aa < 16; aa++) { pr[aa] = pr[aa] * inv * nonzero[aa]; psum += pr[aa]; }
        float deficit = 1.f - psum;
        float nzinv = 1.f / fmaxf(nzsum, 1e-12f);
        float csum = 0.f;
        for (int aa = 0; aa < 16; aa++) {
            float v2 = pr[aa] + nonzero[aa] * nzinv * deficit;
            v2 = fminf(fmaxf(v2, 0.f), 1.f);
            pr[aa] = v2; csum += fabsf(v2);
        }
        float cinv = 1.f / fmaxf(csum, 1e-12f);
        for (int aa = 0; aa < 16; aa++) probs_sm[aa] = pr[aa] * cinv;
    }
    __syncthreads();
    if (tid < 64) {
        int sp = tid;
        const float* row = X + (size_t)(sp * Nn + n) * HGg;
        float np = 0.f, nm = 0.f;
        for (int h = 0; h < 256; h++) {
            float e = e_sm[h];
            np += e * row[2 + 2 * Hh + h];
            nm += e * row[2 + Hh + h];
        }
        float en = enorm_sm;
        float c = row[0];
        float cosp = np / fmaxf(en * nMp[n * 64 + sp], 1e-8f);
        float cosm = nm / fmaxf(en * nMm[n * 64 + sp], 1e-8f);
        float pn = ps_buf[n * 64 + sp] + c * cosp - c * cosm;
        p_buf[n * 64 + sp] = pn;
        out_t[(size_t)n * ROW + 1 + ANa + 1 + Hh + sp] = pn;
    }
    out_t[(size_t)n * ROW + 18 + tid] = s_sm[tid];
    if (tid < 16) out_t[(size_t)n * ROW + 1 + tid] = probs_sm[tid];
    if (tid == 0) {
        out_t[(size_t)n * ROW + 0] = (float)a;
        out_t[(size_t)n * ROW + 17] = v_sm;
    }
}

__global__ void copy_last(float* __restrict__ out, int out_size)
{
    int idx = blockIdx.x * 256 + threadIdx.x;
    if (idx >= Nn * ROW) return;
    int dst = Tt * Nn * ROW + idx;
    if (dst < out_size) out[dst] = out[(Tt - 1) * Nn * ROW + idx];
}

// ---------------- orchestration ----------------
extern "C" void kernel_launch(void* const* d_in, const int* in_sizes, int n_in,
                              void* d_out, int out_size)
{
    const float* base    = (const float*)d_in[0];
    const float* inter   = (const float*)d_in[1];
    const float* hxs     = (const float*)d_in[2];
    const float* emb     = (const float*)d_in[3];
    const float* w_ih    = (const float*)d_in[4];
    const float* w_hh    = (const float*)d_in[5];
    const float* b_ih    = (const float*)d_in[6];
    const float* b_hh    = (const float*)d_in[7];
    const float* conv0_w = (const float*)d_in[8];
    const float* conv0_b = (const float*)d_in[9];
    const float* convs_w = (const float*)d_in[10];
    const float* convs_b = (const float*)d_in[11];
    const float* lin_w   = (const float*)d_in[12];
    const float* lin_b   = (const float*)d_in[13];
    const float* psi_w   = (const float*)d_in[14];
    const float* psi_b   = (const float*)d_in[15];
    const float* actor_w = (const float*)d_in[16];
    const float* actor_b = (const float*)d_in[17];
    const float* critic_w= (const float*)d_in[18];
    const float* critic_b= (const float*)d_in[19];
    const int*   subtasks= (const int*)d_in[20];
    const int*   actions = (const int*)d_in[21];
    float* out = (float*)d_out;

    float *GIv, *GH, *X, *W0t, *linT, *psiT, *p, *ps, *nMp, *nMm, *r, *G, *x0, *x1, *sb, *lp;
    cudaGetSymbolAddress((void**)&GIv,  g_GIv);
    cudaGetSymbolAddress((void**)&GH,   g_GH);
    cudaGetSymbolAddress((void**)&X,    g_X);
    cudaGetSymbolAddress((void**)&W0t,  g_W0t);
    cudaGetSymbolAddress((void**)&linT, g_linT);
    cudaGetSymbolAddress((void**)&psiT, g_psiT);
    cudaGetSymbolAddress((void**)&p,    g_p);
    cudaGetSymbolAddress((void**)&ps,   g_ps);
    cudaGetSymbolAddress((void**)&nMp,  g_nMp);
    cudaGetSymbolAddress((void**)&nMm,  g_nMm);
    cudaGetSymbolAddress((void**)&r,    g_r);
    cudaGetSymbolAddress((void**)&G,    g_G);
    cudaGetSymbolAddress((void**)&x0,   g_x0);
    cudaGetSymbolAddress((void**)&x1,   g_x1);
    cudaGetSymbolAddress((void**)&sb,   g_s);
    cudaGetSymbolAddress((void**)&lp,   g_lp);

    // prologue: weight re-layouts + per-vocab input gates
    transpose_w0 <<<2048, 256>>>(conv0_w, W0t);
    transpose_lin<<<16384, 256>>>(lin_w, linT);
    transpose_psi<<<4096, 256>>>(psi_w, psiT);
    gemm_nt<64,64,16><<<dim3(1, 37, 1), 256>>>(emb, 256, w_ih, 256, GIv, NVv, G3, 256, b_ih, 0);

    // GRU recurrence (64 steps): split-K(4) GEMM + fused gate
    for (int s = 0; s < Ss; s++) {
        if (s > 0)
            gemm_nt<64,64,16><<<dim3(1, 37, 4), 256>>>(X + (size_t)(s - 1) * Nn * HGg, HGg,
                                                       w_hh, HGg, GH, Nn, G3, HGg, nullptr, 0);
        gru_gate<<<(Nn * HGg + 255) / 256, 256>>>(GIv, GH, b_hh, subtasks, X, s);
    }

    norms_kernel<<<Nn * Ss, 128>>>(X, nMp, nMm);
    p_init_kernel<<<Nn, 128>>>(hxs, X, p);

    // scan over T=32 steps
    for (int t = 0; t < Tt; t++) {
        step_a<<<Nn, 256>>>(p, ps, r, X);
        gemm_nt<64,64,16><<<dim3(1, 32, 4), 256>>>(r, 256, W0t, 256, G, Nn, 2048, 256, nullptr, 0);
        step_c<<<dim3(Nn, 4), 256>>>(G, base + (size_t)t * Nn * 512, conv0_b, x0);
        gemm_nt<64,64,16><<<dim3(64, 4, 1), 256>>>(x0, 256, convs_w, 256, x1,
                                                   4096, 256, 256, convs_b, 1);
        gemm_nt<64,64,16><<<dim3(64, 4, 1), 256>>>(x1, 256, convs_w + 65536, 256, x0,
                                                   4096, 256, 256, convs_b + 256, 1);
        gemm_nt<64,64,16><<<dim3(1, 4, 32), 256>>>(x0, 16384, linT, 16384, lp,
                                                   Nn, 256, 16384, nullptr, 0);
        lin_reduce<<<Nn, 256>>>(lp, lin_b, sb);
        step_head<<<Nn, 256>>>(sb, ps, X, nMp, nMm, psiT, psi_b, actor_w, actor_b,
                               critic_w, critic_b, inter + (size_t)t * Nn * 11,
                               actions + t * Nn, p, out + (size_t)t * Nn * ROW);
    }
    copy_last<<<(Nn * ROW + 255) / 256, 256>>>(out, out_size);
}

// round 7
// speedup vs baseline: 1.3931x; 1.3931x over previous
#include <cuda_runtime.h>
#include <cuda_bf16.h>
#include <math.h>

#define Hh 256
#define Ss 64
#define ANa 16
#define Tt 32
#define Nn 64
#define HGg 770   // 2 + 3*H
#define G3 2310   // 3*HG
#define ROW 338   // 1+AN+1+H+S
#define XSTEP (HGg*Nn)      // 49280
#define GSTEP (G3*Nn)       // 147840

// ---------------- scratch ----------------
__device__ float g_GIv[32 * G3];
__device__ float g_GIall[Ss * G3 * Nn];      // [s][j'][n]
__device__ float g_GH[8 * G3 * Nn];          // split-K partials [ks][j'][n]
__device__ float g_Xt[Ss * HGg * Nn];        // GRU out, k-major [s][j][n]
__device__ float g_Xn[Ss * Nn * HGg];        // transposed [s][n][j]
__device__ float g_W0t[2048 * 256];
__device__ float g_linT[256 * 16384];
__device__ float g_psiT[16 * 256 * 256];
__device__ float g_p[Nn * Ss];
__device__ float g_ps[Nn * Ss];
__device__ float g_nMp[Nn * Ss];
__device__ float g_nMm[Nn * Ss];
__device__ float g_r[Nn * 256];
__device__ float g_G[4 * 2048 * Nn];         // [ks][j][n]
__device__ float g_x0[4096 * 256];
__device__ float g_x1[4096 * 256];
__device__ float g_s[Nn * 256];
__device__ float g_lp[64 * 256 * Nn];        // [ks][o][n]

// =========== fast SGEMM: C[kz][M][N] (+bias/relu if ksplit==1) ===========
// C = A(MxK,row,lda) * B^T.  BKM=0: B is [N][K] row-major (ldb=row stride).
//                            BKM=1: B is [K][N] k-major  (ldb=N row stride).
template<int BKM>
__global__ void sgemm128(const float* __restrict__ A, int lda,
                         const float* __restrict__ B, int ldb,
                         float* __restrict__ C, int M, int N, int K,
                         const float* __restrict__ bias, int relu)
{
    __shared__ float As[16][129];
    __shared__ float Bs[16][65];
    int tid = threadIdx.x;                  // 256
    int m0 = blockIdx.x * 128;
    int n0 = blockIdx.y * 64;
    int ksplit = gridDim.z, kz = blockIdx.z;
    int kc = (K + ksplit - 1) / ksplit;
    int kb = kz * kc;
    int ke = min(K, kb + kc);
    int lk = tid & 15, lr = tid >> 4;
    int ty = tid >> 4, tx = tid & 15;

    float acc[8][4];
    #pragma unroll
    for (int i = 0; i < 8; i++)
        #pragma unroll
        for (int j = 0; j < 4; j++) acc[i][j] = 0.f;

    float pa[8], pb[4];
    int nk = (ke > kb) ? ((ke - kb + 15) >> 4) : 0;

    auto ldA = [&](int k0) {
        #pragma unroll
        for (int i = 0; i < 8; i++) {
            int gm = m0 + lr + i * 16, gk = k0 + lk;
            pa[i] = (gm < M && gk < ke) ? A[(size_t)gm * lda + gk] : 0.f;
        }
    };
    auto ldB = [&](int k0) {
        #pragma unroll
        for (int i = 0; i < 4; i++) {
            if (BKM) {
                int gn = n0 + tx + i * 16, gk = k0 + ty;
                pb[i] = (gn < N && gk < ke) ? B[(size_t)gk * ldb + gn] : 0.f;
            } else {
                int gn = n0 + lr + i * 16, gk = k0 + lk;
                pb[i] = (gn < N && gk < ke) ? B[(size_t)gn * ldb + gk] : 0.f;
            }
        }
    };

    if (nk) { ldA(kb); ldB(kb); }
    for (int kt = 0; kt < nk; kt++) {
        #pragma unroll
        for (int i = 0; i < 8; i++) As[lk][lr + i * 16] = pa[i];
        #pragma unroll
        for (int i = 0; i < 4; i++) {
            if (BKM) Bs[ty][tx + i * 16] = pb[i];
            else     Bs[lk][lr + i * 16] = pb[i];
        }
        __syncthreads();
        if (kt + 1 < nk) { ldA(kb + (kt + 1) * 16); ldB(kb + (kt + 1) * 16); }
        #pragma unroll
        for (int kk = 0; kk < 16; kk++) {
            float a_r[8], b_r[4];
            #pragma unroll
            for (int i = 0; i < 8; i++) a_r[i] = As[kk][ty * 8 + i];
            #pragma unroll
            for (int j = 0; j < 4; j++) b_r[j] = Bs[kk][tx * 4 + j];
            #pragma unroll
            for (int i = 0; i < 8; i++)
                #pragma unroll
                for (int j = 0; j < 4; j++) acc[i][j] += a_r[i] * b_r[j];
        }
        __syncthreads();
    }
    float* Cz = C + (size_t)kz * M * N;
    #pragma unroll
    for (int i = 0; i < 8; i++) {
        int gm = m0 + ty * 8 + i;
        if (gm >= M) continue;
        #pragma unroll
        for (int j = 0; j < 4; j++) {
            int gn = n0 + tx * 4 + j;
            if (gn >= N) continue;
            float v = acc[i][j];
            if (ksplit == 1) {
                if (bias) v += bias[gn];
                if (relu) v = fmaxf(v, 0.f);
            }
            Cz[(size_t)gm * N + gn] = v;
        }
    }
}

// ---------------- legacy small GEMM (prologue only) ----------------
template<int TM, int TN, int TK>
__global__ void gemm_nt(const float* __restrict__ A, int lda,
                        const float* __restrict__ B, int ldb,
                        float* __restrict__ C,
                        int M, int N, int K,
                        const float* __restrict__ bias, int relu)
{
    const int NT = (TM / 4) * (TN / 4);
    __shared__ float As[TK][TM + 1];
    __shared__ float Bs[TK][TN + 1];
    int m0 = blockIdx.x * TM;
    int n0 = blockIdx.y * TN;
    int tid = threadIdx.x;
    int ty = tid / (TN / 4);
    int tx = tid % (TN / 4);
    float acc[4][4];
    #pragma unroll
    for (int i = 0; i < 4; i++)
        #pragma unroll
        for (int j = 0; j < 4; j++) acc[i][j] = 0.f;
    for (int k0 = 0; k0 < K; k0 += TK) {
        for (int e = tid; e < TM * TK; e += NT) {
            int mm = e / TK, kk = e % TK;
            int gm = m0 + mm, gk = k0 + kk;
            As[kk][mm] = (gm < M && gk < K) ? A[(size_t)gm * lda + gk] : 0.f;
        }
        for (int e = tid; e < TN * TK; e += NT) {
            int nn = e / TK, kk = e % TK;
            int gn = n0 + nn, gk = k0 + kk;
            Bs[kk][nn] = (gn < N && gk < K) ? B[(size_t)gn * ldb + gk] : 0.f;
        }
        __syncthreads();
        #pragma unroll
        for (int kk = 0; kk < TK; kk++) {
            float a[4], b[4];
            #pragma unroll
            for (int i = 0; i < 4; i++) a[i] = As[kk][ty * 4 + i];
            #pragma unroll
            for (int j = 0; j < 4; j++) b[j] = Bs[kk][tx * 4 + j];
            #pragma unroll
            for (int i = 0; i < 4; i++)
                #pragma unroll
                for (int j = 0; j < 4; j++) acc[i][j] += a[i] * b[j];
        }
        __syncthreads();
    }
    #pragma unroll
    for (int i = 0; i < 4; i++) {
        int gm = m0 + ty * 4 + i;
        if (gm >= M) continue;
        #pragma unroll
        for (int j = 0; j < 4; j++) {
            int gn = n0 + tx * 4 + j;
            if (gn >= N) continue;
            float v = acc[i][j];
            if (bias) v += bias[gn];
            if (relu) v = fmaxf(v, 0.f);
            C[(size_t)gm * N + gn] = v;
        }
    }
}

// ---------------- weight re-layouts ----------------
__global__ void transpose_w0(const float* __restrict__ w, float* __restrict__ wt)
{
    int idx = blockIdx.x * 256 + threadIdx.x;
    if (idx >= 2048 * 256) return;
    int h = idx & 255, j = idx >> 8;
    int o = j >> 3, d = j & 7;
    wt[idx] = w[o * 2048 + h * 8 + d];
}
__global__ void transpose_lin(const float* __restrict__ w, float* __restrict__ wt)
{
    int idx = blockIdx.x * 256 + threadIdx.x;
    if (idx >= 256 * 16384) return;
    int c = idx & 255;
    int p = (idx >> 8) & 63;
    int o = idx >> 14;
    wt[idx] = w[(size_t)o * 16384 + c * 64 + p];
}
__global__ void transpose_psi(const float* __restrict__ w, float* __restrict__ wt)
{
    int idx = blockIdx.x * 256 + threadIdx.x;
    if (idx >= 16 * 256 * 256) return;
    int o = idx & 255;
    int h = (idx >> 8) & 255;
    int a = idx >> 16;
    wt[idx] = w[(size_t)o * 4096 + h * 16 + a];
}

// ---------------- gather per-(s,n) input gates ----------------
__global__ void gather_gi(const float* __restrict__ GIv, const int* __restrict__ subtasks,
                          float* __restrict__ GIall)
{
    int s = blockIdx.x;
    int idx = blockIdx.y * 256 + threadIdx.x;   // over G3*64
    if (idx >= G3 * 64) return;
    int jp = idx >> 6, n = idx & 63;
    int v = subtasks[n * Ss + s];
    GIall[(size_t)s * GSTEP + idx] = GIv[v * G3 + jp];
}

// ---------------- GRU gate (k-major state) ----------------
__global__ void gru_gate(const float* __restrict__ GIall, const float* __restrict__ GH,
                         const float* __restrict__ b_hh, float* __restrict__ Xt, int s)
{
    int idx = blockIdx.x * 256 + threadIdx.x;   // over 770*64
    if (idx >= HGg * Nn) return;
    int j = idx >> 6;
    const float* gia = GIall + (size_t)s * GSTEP;
    float gir = gia[idx];
    float giz = gia[(size_t)(j + HGg) * 64 + (idx & 63)];
    float gin = gia[(size_t)(j + 2 * HGg) * 64 + (idx & 63)];
    float ghr = b_hh[j], ghz = b_hh[HGg + j], ghn = b_hh[2 * HGg + j];
    float hprev = 0.f;
    if (s > 0) {
        int n = idx & 63;
        #pragma unroll
        for (int ks = 0; ks < 8; ks++) {
            const float* g = GH + (size_t)ks * GSTEP;
            ghr += g[(size_t)j * 64 + n];
            ghz += g[(size_t)(j + HGg) * 64 + n];
            ghn += g[(size_t)(j + 2 * HGg) * 64 + n];
        }
        hprev = Xt[(size_t)(s - 1) * XSTEP + idx];
    }
    float r = 1.f / (1.f + expf(-(gir + ghr)));
    float z = 1.f / (1.f + expf(-(giz + ghz)));
    float nn = tanhf(gin + r * ghn);
    Xt[(size_t)s * XSTEP + idx] = (1.f - z) * nn + z * hprev;
}

// ---------------- Xt [s][j][n] -> Xn [s][n][j] ----------------
__global__ void transpose_X(const float* __restrict__ Xt, float* __restrict__ Xn)
{
    __shared__ float tile[64][65];
    int s = blockIdx.x;
    int j0 = blockIdx.y * 64;
    int tid = threadIdx.x;                 // 256
    for (int p = 0; p < 16; p++) {
        int e = p * 256 + tid;
        int jj = e >> 6, nn = e & 63;
        if (j0 + jj < HGg)
            tile[jj][nn] = Xt[(size_t)s * XSTEP + (size_t)(j0 + jj) * 64 + nn];
    }
    __syncthreads();
    for (int p = 0; p < 16; p++) {
        int e = p * 256 + tid;
        int nn = e >> 6, jj = e & 63;
        if (j0 + jj < HGg)
            Xn[(size_t)(s * Nn + nn) * HGg + j0 + jj] = tile[jj][nn];
    }
}

// ---------------- loop-invariant norms ----------------
__global__ void norms_kernel(const float* __restrict__ X, float* __restrict__ nMp, float* __restrict__ nMm)
{
    int b = blockIdx.x;
    int n = b >> 6, sp = b & 63;
    const float* row = X + (size_t)(sp * Nn + n) * HGg;
    __shared__ float rp[128], rm[128];
    int tid = threadIdx.x;
    float ap = 0.f, am = 0.f;
    for (int h = tid; h < 256; h += 128) {
        float x = row[2 + 2 * Hh + h]; ap += x * x;
        float y = row[2 + Hh + h];     am += y * y;
    }
    rp[tid] = ap; rm[tid] = am;
    __syncthreads();
    for (int off = 64; off > 0; off >>= 1) {
        if (tid < off) { rp[tid] += rp[tid + off]; rm[tid] += rm[tid + off]; }
        __syncthreads();
    }
    if (tid == 0) { nMp[b] = sqrtf(rp[0]); nMm[b] = sqrtf(rm[0]); }
}

// ---------------- p_init ----------------
__global__ void p_init_kernel(const float* __restrict__ hxs, const float* __restrict__ X, float* __restrict__ p)
{
    int n = blockIdx.x;
    __shared__ int anynz;
    if (threadIdx.x == 0) anynz = 0;
    __syncthreads();
    for (int i = threadIdx.x; i < ROW; i += blockDim.x)
        if (hxs[n * ROW + i] != 0.f) atomicOr(&anynz, 1);
    __syncthreads();
    bool newep = (anynz == 0);
    for (int sp = threadIdx.x; sp < Ss; sp += blockDim.x) {
        float p0 = X[(size_t)(sp * Nn + n) * HGg + 1];
        p[n * Ss + sp] = newep ? p0 : hxs[n * ROW + 1 + ANa + 1 + Hh + sp];
    }
}

// ---------------- step A: softmax + r = ps @ M ----------------
__global__ void step_a(const float* __restrict__ p, float* __restrict__ ps_out,
                       float* __restrict__ r_out, const float* __restrict__ X)
{
    int n = blockIdx.x;
    __shared__ float ps[64];
    __shared__ float tmp[64];
    int tid = threadIdx.x;              // 256
    if (tid < 64) tmp[tid] = p[n * 64 + tid];
    __syncthreads();
    if (tid == 0) {
        float m = tmp[0];
        for (int i = 1; i < 64; i++) m = fmaxf(m, tmp[i]);
        float sum = 0.f;
        for (int i = 0; i < 64; i++) { float e = expf(tmp[i] - m); ps[i] = e; sum += e; }
        float inv = 1.f / sum;
        for (int i = 0; i < 64; i++) ps[i] *= inv;
    }
    __syncthreads();
    if (tid < 64) ps_out[n * 64 + tid] = ps[tid];
    float acc = 0.f;
    for (int s = 0; s < 64; s++)
        acc += ps[s] * X[(size_t)(s * Nn + n) * HGg + 2 + tid];
    r_out[n * 256 + tid] = acc;
}

// ---------------- step C: s0 = relu(conv0 dot-8), G is [ks][j][n] ----------------
__global__ void step_c(const float* __restrict__ Gpart, const float* __restrict__ base_t,
                       const float* __restrict__ b0, float* __restrict__ out)
{
    int n = blockIdx.x;
    int o0 = blockIdx.y * 64;
    __shared__ float bs[8 * 64];
    __shared__ float Gs[64 * 8];
    int tid = threadIdx.x;              // 256
    for (int e = tid; e < 512; e += 256) bs[e] = base_t[n * 512 + e];
    for (int e = tid; e < 512; e += 256) {
        int j = o0 * 8 + e;
        float v = 0.f;
        #pragma unroll
        for (int ks = 0; ks < 4; ks++) v += Gpart[((size_t)ks * 2048 + j) * 64 + n];
        Gs[e] = v;
    }
    __syncthreads();
    int o_l = tid & 63;
    int pg = tid >> 6;
    float bias = b0[o0 + o_l];
    for (int k = 0; k < 16; k++) {
        int pp = pg * 16 + k;
        float acc = bias;
        #pragma unroll
        for (int d = 0; d < 8; d++) acc += Gs[o_l * 8 + d] * bs[d * 64 + pp];
        out[((size_t)n * 64 + pp) * 256 + o0 + o_l] = fmaxf(acc, 0.f);
    }
}

// ---------------- lin split-K reduce: partials [ks][o][n] -> s[n][o] ----------------
__global__ void lin_reduce(const float* __restrict__ part, const float* __restrict__ bias,
                           float* __restrict__ s_out)
{
    int idx = blockIdx.x * 256 + threadIdx.x;    // 256*64, idx = o*64+n
    int o = idx >> 6, n = idx & 63;
    float v = bias[o];
    for (int ks = 0; ks < 64; ks++) v += part[(size_t)ks * 256 * 64 + idx];
    s_out[n * 256 + o] = fmaxf(v, 0.f);
}

// ---------------- step head ----------------
__global__ void step_head(
    const float* __restrict__ s_buf, const float* __restrict__ ps_buf,
    const float* __restrict__ X, const float* __restrict__ nMp, const float* __restrict__ nMm,
    const float* __restrict__ psiT, const float* __restrict__ psi_b,
    const float* __restrict__ actor_w, const float* __restrict__ actor_b,
    const float* __restrict__ critic_w, const float* __restrict__ critic_b,
    const float* __restrict__ inter_t, const int* __restrict__ act_t,
    float* __restrict__ p_buf, float* __restrict__ out_t)
{
    int n = blockIdx.x;
    int tid = threadIdx.x;              // 256
    __shared__ float s_sm[256];
    __shared__ float e_sm[256];
    __shared__ float red[256];
    __shared__ float logit_sm[16];
    __shared__ float probs_sm[16];
    __shared__ float v_sm;
    __shared__ float enorm_sm;
    s_sm[tid] = s_buf[n * 256 + tid];
    __syncthreads();
    int a = act_t[n];
    {
        float acc = psi_b[tid];
        const float* P = psiT + (size_t)a * 256 * 256;
        for (int h = 0; h < 256; h++) acc += P[h * 256 + tid] * s_sm[h];
        e_sm[tid] = acc;
        red[tid] = acc * acc;
    }
    __syncthreads();
    for (int off = 128; off > 0; off >>= 1) {
        if (tid < off) red[tid] += red[tid + off];
        __syncthreads();
    }
    if (tid == 0) enorm_sm = sqrtf(red[0]);
    if (tid < 16) {
        float acc = actor_b[tid];
        for (int h = 0; h < 256; h++) acc += actor_w[tid * 256 + h] * s_sm[h];
        logit_sm[tid] = acc;
    } else if (tid == 32) {
        float acc = critic_b[0];
        for (int h = 0; h < 256; h++) acc += critic_w[h] * s_sm[h];
        v_sm = acc;
    }
    __syncthreads();
    if (tid == 0) {
        float pr[16], nonzero[16];
        float mx = logit_sm[0];
        for (int aa = 1; aa < 16; aa++) mx = fmaxf(mx, logit_sm[aa]);
        float sum = 0.f;
        for (int aa = 0; aa < 16; aa++) { pr[aa] = expf(logit_sm[aa] - mx); sum += pr[aa]; }
        float inv = 1.f / sum;
        float nzsum = 0.f;
        for (int aa = 0; aa < 16; aa++) {
            float nz = (aa < 5) ? 1.f : inter_t[n * 11 + aa - 5];
            nonzero[aa] = nz; nzsum += fabsf(nz);
        }
        float psum = 0.f;
        for (int aa = 0; aa < 16; aa++) { pr[aa] = pr[aa] * inv * nonzero[aa]; psum += pr[aa]; }
        float deficit = 1.f - psum;
        float nzinv = 1.f / fmaxf(nzsum, 1e-12f);
        float csum = 0.f;
        for (int aa = 0; aa < 16; aa++) {
            float v2 = pr[aa] + nonzero[aa] * nzinv * deficit;
            v2 = fminf(fmaxf(v2, 0.f), 1.f);
            pr[aa] = v2; csum += fabsf(v2);
        }
        float cinv = 1.f / fmaxf(csum, 1e-12f);
        for (int aa = 0; aa < 16; aa++) probs_sm[aa] = pr[aa] * cinv;
    }
    __syncthreads();
    if (tid < 64) {
        int sp = tid;
        const float* row = X + (size_t)(sp * Nn + n) * HGg;
        float np = 0.f, nm = 0.f;
        for (int h = 0; h < 256; h++) {
            float e = e_sm[h];
            np += e * row[2 + 2 * Hh + h];
            nm += e * row[2 + Hh + h];
        }
        float en = enorm_sm;
        float c = row[0];
        float cosp = np / fmaxf(en * nMp[n * 64 + sp], 1e-8f);
        float cosm = nm / fmaxf(en * nMm[n * 64 + sp], 1e-8f);
        float pn = ps_buf[n * 64 + sp] + c * cosp - c * cosm;
        p_buf[n * 64 + sp] = pn;
        out_t[(size_t)n * ROW + 1 + ANa + 1 + Hh + sp] = pn;
    }
    out_t[(size_t)n * ROW + 18 + tid] = s_sm[tid];
    if (tid < 16) out_t[(size_t)n * ROW + 1 + tid] = probs_sm[tid];
    if (tid == 0) {
        out_t[(size_t)n * ROW + 0] = (float)a;
        out_t[(size_t)n * ROW + 17] = v_sm;
    }
}

__global__ void copy_last(float* __restrict__ out, int out_size)
{
    int idx = blockIdx.x * 256 + threadIdx.x;
    if (idx >= Nn * ROW) return;
    int dst = Tt * Nn * ROW + idx;
    if (dst < out_size) out[dst] = out[(Tt - 1) * Nn * ROW + idx];
}

// ---------------- orchestration ----------------
extern "C" void kernel_launch(void* const* d_in, const int* in_sizes, int n_in,
                              void* d_out, int out_size)
{
    const float* base    = (const float*)d_in[0];
    const float* inter   = (const float*)d_in[1];
    const float* hxs     = (const float*)d_in[2];
    const float* emb     = (const float*)d_in[3];
    const float* w_ih    = (const float*)d_in[4];
    const float* w_hh    = (const float*)d_in[5];
    const float* b_ih    = (const float*)d_in[6];
    const float* b_hh    = (const float*)d_in[7];
    const float* conv0_w = (const float*)d_in[8];
    const float* conv0_b = (const float*)d_in[9];
    const float* convs_w = (const float*)d_in[10];
    const float* convs_b = (const float*)d_in[11];
    const float* lin_w   = (const float*)d_in[12];
    const float* lin_b   = (const float*)d_in[13];
    const float* psi_w   = (const float*)d_in[14];
    const float* psi_b   = (const float*)d_in[15];
    const float* actor_w = (const float*)d_in[16];
    const float* actor_b = (const float*)d_in[17];
    const float* critic_w= (const float*)d_in[18];
    const float* critic_b= (const float*)d_in[19];
    const int*   subtasks= (const int*)d_in[20];
    const int*   actions = (const int*)d_in[21];
    float* out = (float*)d_out;

    float *GIv, *GIall, *GH, *Xt, *Xn, *W0t, *linT, *psiT, *p, *ps, *nMp, *nMm, *r, *G, *x0, *x1, *sb, *lp;
    cudaGetSymbolAddress((void**)&GIv,   g_GIv);
    cudaGetSymbolAddress((void**)&GIall, g_GIall);
    cudaGetSymbolAddress((void**)&GH,    g_GH);
    cudaGetSymbolAddress((void**)&Xt,    g_Xt);
    cudaGetSymbolAddress((void**)&Xn,    g_Xn);
    cudaGetSymbolAddress((void**)&W0t,   g_W0t);
    cudaGetSymbolAddress((void**)&linT,  g_linT);
    cudaGetSymbolAddress((void**)&psiT,  g_psiT);
    cudaGetSymbolAddress((void**)&p,     g_p);
    cudaGetSymbolAddress((void**)&ps,    g_ps);
    cudaGetSymbolAddress((void**)&nMp,   g_nMp);
    cudaGetSymbolAddress((void**)&nMm,   g_nMm);
    cudaGetSymbolAddress((void**)&r,     g_r);
    cudaGetSymbolAddress((void**)&G,     g_G);
    cudaGetSymbolAddress((void**)&x0,    g_x0);
    cudaGetSymbolAddress((void**)&x1,    g_x1);
    cudaGetSymbolAddress((void**)&sb,    g_s);
    cudaGetSymbolAddress((void**)&lp,    g_lp);

    // prologue
    transpose_w0 <<<2048, 256>>>(conv0_w, W0t);
    transpose_lin<<<16384, 256>>>(lin_w, linT);
    transpose_psi<<<4096, 256>>>(psi_w, psiT);
    gemm_nt<64,64,16><<<dim3(1, 37, 1), 256>>>(emb, 256, w_ih, 256, GIv, 32, G3, 256, b_ih, 0);
    gather_gi<<<dim3(Ss, (G3 * 64 + 255) / 256), 256>>>(GIv, subtasks, GIall);

    // GRU recurrence
    for (int s = 0; s < Ss; s++) {
        if (s > 0)
            sgemm128<1><<<dim3(19, 1, 8), 256>>>(w_hh, HGg, Xt + (size_t)(s - 1) * XSTEP, 64,
                                                 GH, G3, 64, HGg, nullptr, 0);
        gru_gate<<<(HGg * Nn + 255) / 256, 256>>>(GIall, GH, b_hh, Xt, s);
    }
    transpose_X<<<dim3(Ss, 13), 256>>>(Xt, Xn);

    norms_kernel<<<Nn * Ss, 128>>>(Xn, nMp, nMm);
    p_init_kernel<<<Nn, 128>>>(hxs, Xn, p);

    // scan over T=32 steps
    for (int t = 0; t < Tt; t++) {
        step_a<<<Nn, 256>>>(p, ps, r, Xn);
        sgemm128<0><<<dim3(16, 1, 4), 256>>>(W0t, 256, r, 256, G, 2048, 64, 256, nullptr, 0);
        step_c<<<dim3(Nn, 4), 256>>>(G, base + (size_t)t * Nn * 512, conv0_b, x0);
        sgemm128<0><<<dim3(32, 4, 1), 256>>>(x0, 256, convs_w, 256, x1,
                                             4096, 256, 256, convs_b, 1);
        sgemm128<0><<<dim3(32, 4, 1), 256>>>(x1, 256, convs_w + 65536, 256, x0,
                                             4096, 256, 256, convs_b + 256, 1);
        sgemm128<0><<<dim3(2, 1, 64), 256>>>(linT, 16384, x0, 16384, lp,
                                             256, 64, 16384, nullptr, 0);
        lin_reduce<<<Nn, 256>>>(lp, lin_b, sb);
        step_head<<<Nn, 256>>>(sb, ps, Xn, nMp, nMm, psiT, psi_b, actor_w, actor_b,
                               critic_w, critic_b, inter + (size_t)t * Nn * 11,
                               actions + t * Nn, p, out + (size_t)t * Nn * ROW);
    }
    copy_last<<<(Nn * ROW + 255) / 256, 256>>>(out, out_size);
}

// round 8
// speedup vs baseline: 2.1960x; 1.5764x over previous
#include <cuda_runtime.h>
#include <cuda_bf16.h>
#include <math.h>

#define Hh 256
#define Ss 64
#define ANa 16
#define Tt 32
#define Nn 64
#define HGg 770   // 2 + 3*H
#define G3 2310   // 3*HG
#define ROW 338   // 1+AN+1+H+S
#define KP 800    // padded GRU K
#define XSTEP (KP*Nn)       // padded Xt step: [800][64]
#define GSTEP (G3*Nn)       // gate-matrix step

// ---------------- scratch ----------------
__device__ float g_GIvT[G3 * 32];            // [j'][v]
__device__ float g_GIall[Ss * G3 * Nn];      // [s][j'][n]
__device__ float g_GH[10 * G3 * Nn];         // split-K partials [ks][j'][n]
__device__ float g_whhP[G3 * KP];            // padded w_hh [2310][800]
__device__ float g_Xt[Ss * KP * Nn];         // GRU out k-major [s][j(800)][n]
__device__ float g_Xn[Ss * Nn * HGg];        // [s][n][j]
__device__ float g_W0t[2048 * 256];
__device__ float g_linT[256 * 16384];
__device__ float g_psiT[16 * 256 * 256];
__device__ float g_p[Nn * Ss];
__device__ float g_ps[Nn * Ss];
__device__ float g_nMp[Nn * Ss];
__device__ float g_nMm[Nn * Ss];
__device__ float g_r[Nn * 256];
__device__ float g_G[4 * 2048 * Nn];         // [ks][j][n]
__device__ float g_x0[4096 * 256];
__device__ float g_x1[4096 * 256];
__device__ float g_s[Nn * 256];
__device__ float g_lp[64 * 256 * Nn];        // [ks][o][n]

// =========== SGEMM: C[kz][M][N] = A(MxK,lda) * B^T (+bias/relu if ksplit==1) ===========
// BKM=0: B is [N][K] row-major. BKM=1: B is [K][N] k-major.
// Requirements: lda%4==0, ldb%4==0, K % (16*gridDim.z) == 0.
template<int BKM>
__global__ void __launch_bounds__(256, 2)
sg(const float* __restrict__ A, int lda,
   const float* __restrict__ B, int ldb,
   float* __restrict__ C, int M, int N, int K,
   const float* __restrict__ bias, int relu)
{
    __shared__ float As[2][16][132];
    __shared__ float Bs[2][16][68];
    const int tid = threadIdx.x;
    const int m0 = blockIdx.x * 128;
    const int n0 = blockIdx.y * 64;
    const int ksplit = gridDim.z, kz = blockIdx.z;
    const int kc = K / ksplit;
    const int kb = kz * kc;
    const int nk = kc >> 4;

    const int am = tid >> 1;            // 0..127
    const int ak = (tid & 1) * 8;       // 0 or 8
    const int bn = tid >> 2, bk4 = (tid & 3) * 4;   // BKM=0 loader
    const int bk = tid >> 4, bn4 = (tid & 15) * 4;  // BKM=1 loader
    const int ty = tid >> 4, tx = tid & 15;

    float4 pa0, pa1, pb;
    const float4 z4 = make_float4(0.f, 0.f, 0.f, 0.f);

    auto ldg = [&](int kt) {
        int k0 = kb + kt * 16;
        if (m0 + am < M) {
            const float* ap = A + (size_t)(m0 + am) * lda + k0 + ak;
            pa0 = *(const float4*)ap;
            pa1 = *(const float4*)(ap + 4);
        } else { pa0 = z4; pa1 = z4; }
        if (BKM) {
            pb = *(const float4*)(B + (size_t)(k0 + bk) * ldb + n0 + bn4);
        } else {
            if (n0 + bn < N)
                pb = *(const float4*)(B + (size_t)(n0 + bn) * ldb + k0 + bk4);
            else pb = z4;
        }
    };
    auto sts = [&](int buf) {
        As[buf][ak + 0][am] = pa0.x; As[buf][ak + 1][am] = pa0.y;
        As[buf][ak + 2][am] = pa0.z; As[buf][ak + 3][am] = pa0.w;
        As[buf][ak + 4][am] = pa1.x; As[buf][ak + 5][am] = pa1.y;
        As[buf][ak + 6][am] = pa1.z; As[buf][ak + 7][am] = pa1.w;
        if (BKM) {
            *(float4*)&Bs[buf][bk][bn4] = pb;
        } else {
            Bs[buf][bk4 + 0][bn] = pb.x; Bs[buf][bk4 + 1][bn] = pb.y;
            Bs[buf][bk4 + 2][bn] = pb.z; Bs[buf][bk4 + 3][bn] = pb.w;
        }
    };

    float acc[8][4];
    #pragma unroll
    for (int i = 0; i < 8; i++)
        #pragma unroll
        for (int j = 0; j < 4; j++) acc[i][j] = 0.f;

    ldg(0); sts(0); __syncthreads();
    for (int kt = 0; kt < nk; kt++) {
        if (kt + 1 < nk) ldg(kt + 1);
        const int buf = kt & 1;
        #pragma unroll
        for (int kk = 0; kk < 16; kk++) {
            float4 a0 = *(const float4*)&As[buf][kk][ty * 8];
            float4 a1 = *(const float4*)&As[buf][kk][ty * 8 + 4];
            float4 b  = *(const float4*)&Bs[buf][kk][tx * 4];
            float av[8] = {a0.x, a0.y, a0.z, a0.w, a1.x, a1.y, a1.z, a1.w};
            float bv[4] = {b.x, b.y, b.z, b.w};
            #pragma unroll
            for (int i = 0; i < 8; i++)
                #pragma unroll
                for (int j = 0; j < 4; j++) acc[i][j] += av[i] * bv[j];
        }
        if (kt + 1 < nk) sts(buf ^ 1);
        __syncthreads();
    }

    float* Cz = C + (size_t)kz * M * N;
    #pragma unroll
    for (int i = 0; i < 8; i++) {
        int gm = m0 + ty * 8 + i;
        if (gm >= M) continue;
        int gn = n0 + tx * 4;
        if (gn + 3 < N) {
            float4 v = make_float4(acc[i][0], acc[i][1], acc[i][2], acc[i][3]);
            if (ksplit == 1) {
                if (bias) { v.x += bias[gn]; v.y += bias[gn+1]; v.z += bias[gn+2]; v.w += bias[gn+3]; }
                if (relu) { v.x = fmaxf(v.x,0.f); v.y = fmaxf(v.y,0.f); v.z = fmaxf(v.z,0.f); v.w = fmaxf(v.w,0.f); }
            }
            *(float4*)&Cz[(size_t)gm * N + gn] = v;
        } else {
            #pragma unroll
            for (int j = 0; j < 4; j++) {
                if (gn + j >= N) continue;
                float v = acc[i][j];
                if (ksplit == 1) {
                    if (bias) v += bias[gn + j];
                    if (relu) v = fmaxf(v, 0.f);
                }
                Cz[(size_t)gm * N + gn + j] = v;
            }
        }
    }
}

// ---------------- weight re-layouts ----------------
__global__ void transpose_w0(const float* __restrict__ w, float* __restrict__ wt)
{
    int idx = blockIdx.x * 256 + threadIdx.x;
    if (idx >= 2048 * 256) return;
    int h = idx & 255, j = idx >> 8;
    int o = j >> 3, d = j & 7;
    wt[idx] = w[o * 2048 + h * 8 + d];
}
__global__ void transpose_lin(const float* __restrict__ w, float* __restrict__ wt)
{
    int idx = blockIdx.x * 256 + threadIdx.x;
    if (idx >= 256 * 16384) return;
    int c = idx & 255;
    int p = (idx >> 8) & 63;
    int o = idx >> 14;
    wt[idx] = w[(size_t)o * 16384 + c * 64 + p];
}
__global__ void transpose_psi(const float* __restrict__ w, float* __restrict__ wt)
{
    int idx = blockIdx.x * 256 + threadIdx.x;
    if (idx >= 16 * 256 * 256) return;
    int o = idx & 255;
    int h = (idx >> 8) & 255;
    int a = idx >> 16;
    wt[idx] = w[(size_t)o * 4096 + h * 16 + a];
}
__global__ void pad_whh(const float* __restrict__ w, float* __restrict__ wp)
{
    int idx = blockIdx.x * 256 + threadIdx.x;   // G3*KP
    if (idx >= G3 * KP) return;
    int k = idx % KP, j = idx / KP;
    wp[idx] = (k < HGg) ? w[j * HGg + k] : 0.f;
}
__global__ void zero_xt_pad(float* __restrict__ Xt)
{
    int idx = blockIdx.x * 256 + threadIdx.x;   // Ss*30*64
    if (idx >= Ss * (KP - HGg) * Nn) return;
    int n = idx & 63;
    int jj = (idx >> 6) % (KP - HGg);
    int s = idx / ((KP - HGg) * Nn);
    Xt[(size_t)s * XSTEP + (size_t)(HGg + jj) * 64 + n] = 0.f;
}

// ---------------- gather per-(s,n) input gates ----------------
__global__ void gather_gi(const float* __restrict__ GIvT, const int* __restrict__ subtasks,
                          float* __restrict__ GIall)
{
    int s = blockIdx.x;
    int idx = blockIdx.y * 256 + threadIdx.x;   // over G3*64
    if (idx >= G3 * 64) return;
    int jp = idx >> 6, n = idx & 63;
    int v = subtasks[n * Ss + s];
    GIall[(size_t)s * GSTEP + idx] = GIvT[jp * 32 + v];
}

// ---------------- GRU gate (k-major state, 10 partials, b_ih folded) ----------------
__global__ void gru_gate(const float* __restrict__ GIall, const float* __restrict__ GH,
                         const float* __restrict__ b_ih, const float* __restrict__ b_hh,
                         float* __restrict__ Xt, int s)
{
    int idx = blockIdx.x * 256 + threadIdx.x;   // over 770*64
    if (idx >= HGg * Nn) return;
    int j = idx >> 6, n = idx & 63;
    const float* gia = GIall + (size_t)s * GSTEP;
    float gir = gia[(size_t)j * 64 + n]            + b_ih[j];
    float giz = gia[(size_t)(j + HGg) * 64 + n]    + b_ih[HGg + j];
    float gin = gia[(size_t)(j + 2 * HGg) * 64 + n] + b_ih[2 * HGg + j];
    float ghr = b_hh[j], ghz = b_hh[HGg + j], ghn = b_hh[2 * HGg + j];
    float hprev = 0.f;
    if (s > 0) {
        #pragma unroll
        for (int ks = 0; ks < 10; ks++) {
            const float* g = GH + (size_t)ks * GSTEP;
            ghr += g[(size_t)j * 64 + n];
            ghz += g[(size_t)(j + HGg) * 64 + n];
            ghn += g[(size_t)(j + 2 * HGg) * 64 + n];
        }
        hprev = Xt[(size_t)(s - 1) * XSTEP + (size_t)j * 64 + n];
    }
    float r = 1.f / (1.f + expf(-(gir + ghr)));
    float z = 1.f / (1.f + expf(-(giz + ghz)));
    float nn = tanhf(gin + r * ghn);
    Xt[(size_t)s * XSTEP + (size_t)j * 64 + n] = (1.f - z) * nn + z * hprev;
}

// ---------------- Xt [s][j][n] -> Xn [s][n][j] ----------------
__global__ void transpose_X(const float* __restrict__ Xt, float* __restrict__ Xn)
{
    __shared__ float tile[64][65];
    int s = blockIdx.x;
    int j0 = blockIdx.y * 64;
    int tid = threadIdx.x;                 // 256
    for (int p = 0; p < 16; p++) {
        int e = p * 256 + tid;
        int jj = e >> 6, nn = e & 63;
        if (j0 + jj < HGg)
            tile[jj][nn] = Xt[(size_t)s * XSTEP + (size_t)(j0 + jj) * 64 + nn];
    }
    __syncthreads();
    for (int p = 0; p < 16; p++) {
        int e = p * 256 + tid;
        int nn = e >> 6, jj = e & 63;
        if (j0 + jj < HGg)
            Xn[(size_t)(s * Nn + nn) * HGg + j0 + jj] = tile[jj][nn];
    }
}

// ---------------- loop-invariant norms ----------------
__global__ void norms_kernel(const float* __restrict__ X, float* __restrict__ nMp, float* __restrict__ nMm)
{
    int b = blockIdx.x;
    int n = b >> 6, sp = b & 63;
    const float* row = X + (size_t)(sp * Nn + n) * HGg;
    __shared__ float rp[128], rm[128];
    int tid = threadIdx.x;
    float ap = 0.f, am = 0.f;
    for (int h = tid; h < 256; h += 128) {
        float x = row[2 + 2 * Hh + h]; ap += x * x;
        float y = row[2 + Hh + h];     am += y * y;
    }
    rp[tid] = ap; rm[tid] = am;
    __syncthreads();
    for (int off = 64; off > 0; off >>= 1) {
        if (tid < off) { rp[tid] += rp[tid + off]; rm[tid] += rm[tid + off]; }
        __syncthreads();
    }
    if (tid == 0) { nMp[b] = sqrtf(rp[0]); nMm[b] = sqrtf(rm[0]); }
}

// ---------------- p_init ----------------
__global__ void p_init_kernel(const float* __restrict__ hxs, const float* __restrict__ X, float* __restrict__ p)
{
    int n = blockIdx.x;
    __shared__ int anynz;
    if (threadIdx.x == 0) anynz = 0;
    __syncthreads();
    for (int i = threadIdx.x; i < ROW; i += blockDim.x)
        if (hxs[n * ROW + i] != 0.f) atomicOr(&anynz, 1);
    __syncthreads();
    bool newep = (anynz == 0);
    for (int sp = threadIdx.x; sp < Ss; sp += blockDim.x) {
        float p0 = X[(size_t)(sp * Nn + n) * HGg + 1];
        p[n * Ss + sp] = newep ? p0 : hxs[n * ROW + 1 + ANa + 1 + Hh + sp];
    }
}

// ---------------- initial softmax + r (t=0 only) ----------------
__global__ void step_a(const float* __restrict__ p, float* __restrict__ ps_out,
                       float* __restrict__ r_out, const float* __restrict__ X)
{
    int n = blockIdx.x;
    __shared__ float ps[64];
    __shared__ float tmp[64];
    int tid = threadIdx.x;              // 256
    if (tid < 64) tmp[tid] = p[n * 64 + tid];
    __syncthreads();
    if (tid == 0) {
        float m = tmp[0];
        for (int i = 1; i < 64; i++) m = fmaxf(m, tmp[i]);
        float sum = 0.f;
        for (int i = 0; i < 64; i++) { float e = expf(tmp[i] - m); ps[i] = e; sum += e; }
        float inv = 1.f / sum;
        for (int i = 0; i < 64; i++) ps[i] *= inv;
    }
    __syncthreads();
    if (tid < 64) ps_out[n * 64 + tid] = ps[tid];
    float acc = 0.f;
    for (int s = 0; s < 64; s++)
        acc += ps[s] * X[(size_t)(s * Nn + n) * HGg + 2 + tid];
    r_out[n * 256 + tid] = acc;
}

// ---------------- step C: s0 = relu(conv0 dot-8), G is [ks][j][n] ----------------
__global__ void step_c(const float* __restrict__ Gpart, const float* __restrict__ base_t,
                       const float* __restrict__ b0, float* __restrict__ out)
{
    int n = blockIdx.x;
    int o0 = blockIdx.y * 64;
    __shared__ float bs[8 * 64];
    __shared__ float Gs[64 * 8];
    int tid = threadIdx.x;              // 256
    for (int e = tid; e < 512; e += 256) bs[e] = base_t[n * 512 + e];
    for (int e = tid; e < 512; e += 256) {
        int j = o0 * 8 + e;
        float v = 0.f;
        #pragma unroll
        for (int ks = 0; ks < 4; ks++) v += Gpart[((size_t)ks * 2048 + j) * 64 + n];
        Gs[e] = v;
    }
    __syncthreads();
    int o_l = tid & 63;
    int pg = tid >> 6;
    float bias = b0[o0 + o_l];
    for (int k = 0; k < 16; k++) {
        int pp = pg * 16 + k;
        float acc = bias;
        #pragma unroll
        for (int d = 0; d < 8; d++) acc += Gs[o_l * 8 + d] * bs[d * 64 + pp];
        out[((size_t)n * 64 + pp) * 256 + o0 + o_l] = fmaxf(acc, 0.f);
    }
}

// ---------------- lin split-K reduce: partials [ks][o][n] -> s[n][o] ----------------
__global__ void lin_reduce(const float* __restrict__ part, const float* __restrict__ bias,
                           float* __restrict__ s_out)
{
    int idx = blockIdx.x * 256 + threadIdx.x;    // idx = o*64+n
    int o = idx >> 6, n = idx & 63;
    float v = bias[o];
    for (int ks = 0; ks < 64; ks++) v += part[(size_t)ks * 256 * 64 + idx];
    s_out[n * 256 + o] = fmaxf(v, 0.f);
}

// ---------------- step head (+ fused softmax & r for next step) ----------------
__global__ void step_head(
    const float* __restrict__ s_buf, float* __restrict__ ps_buf,
    const float* __restrict__ X, const float* __restrict__ nMp, const float* __restrict__ nMm,
    const float* __restrict__ psiT, const float* __restrict__ psi_b,
    const float* __restrict__ actor_w, const float* __restrict__ actor_b,
    const float* __restrict__ critic_w, const float* __restrict__ critic_b,
    const float* __restrict__ inter_t, const int* __restrict__ act_t,
    float* __restrict__ r_out, float* __restrict__ out_t)
{
    int n = blockIdx.x;
    int tid = threadIdx.x;              // 256
    __shared__ float s_sm[256];
    __shared__ float e_sm[256];
    __shared__ float red[256];
    __shared__ float logit_sm[16];
    __shared__ float probs_sm[16];
    __shared__ float ps_sm[64];
    __shared__ float pn_sm[64];
    __shared__ float v_sm;
    __shared__ float enorm_sm;
    s_sm[tid] = s_buf[n * 256 + tid];
    if (tid < 64) ps_sm[tid] = ps_buf[n * 64 + tid];
    __syncthreads();
    int a = act_t[n];
    {
        float acc = psi_b[tid];
        const float* P = psiT + (size_t)a * 256 * 256;
        for (int h = 0; h < 256; h++) acc += P[h * 256 + tid] * s_sm[h];
        e_sm[tid] = acc;
        red[tid] = acc * acc;
    }
    __syncthreads();
    for (int off = 128; off > 0; off >>= 1) {
        if (tid < off) red[tid] += red[tid + off];
        __syncthreads();
    }
    if (tid == 0) enorm_sm = sqrtf(red[0]);
    if (tid < 16) {
        float acc = actor_b[tid];
        for (int h = 0; h < 256; h++) acc += actor_w[tid * 256 + h] * s_sm[h];
        logit_sm[tid] = acc;
    } else if (tid == 32) {
        float acc = critic_b[0];
        for (int h = 0; h < 256; h++) acc += critic_w[h] * s_sm[h];
        v_sm = acc;
    }
    __syncthreads();
    if (tid == 0) {
        float pr[16], nonzero[16];
        float mx = logit_sm[0];
        for (int aa = 1; aa < 16; aa++) mx = fmaxf(mx, logit_sm[aa]);
        float sum = 0.f;
        for (int aa = 0; aa < 16; aa++) { pr[aa] = expf(logit_sm[aa] - mx); sum += pr[aa]; }
        float inv = 1.f / sum;
        float nzsum = 0.f;
        for (int aa = 0; aa < 16; aa++) {
            float nz = (aa < 5) ? 1.f : inter_t[n * 11 + aa - 5];
            nonzero[aa] = nz; nzsum += fabsf(nz);
        }
        float psum = 0.f;
        for (int aa = 0; aa < 16; aa++) { pr[aa] = pr[aa] * inv * nonzero[aa]; psum += pr[aa]; }
        float deficit = 1.f - psum;
        float nzinv = 1.f / fmaxf(nzsum, 1e-12f);
        float csum = 0.f;
        for (int aa = 0; aa < 16; aa++) {
            float v2 = pr[aa] + nonzero[aa] * nzinv * deficit;
            v2 = fminf(fmaxf(v2, 0.f), 1.f);
            pr[aa] = v2; csum += fabsf(v2);
        }
        float cinv = 1.f / fmaxf(csum, 1e-12f);
        for (int aa = 0; aa < 16; aa++) probs_sm[aa] = pr[aa] * cinv;
    }
    __syncthreads();
    if (tid < 64) {
        int sp = tid;
        const float* row = X + (size_t)(sp * Nn + n) * HGg;
        float np = 0.f, nm = 0.f;
        for (int h = 0; h < 256; h++) {
            float e = e_sm[h];
            np += e * row[2 + 2 * Hh + h];
            nm += e * row[2 + Hh + h];
        }
        float en = enorm_sm;
        float c = row[0];
        float cosp = np / fmaxf(en * nMp[n * 64 + sp], 1e-8f);
        float cosm = nm / fmaxf(en * nMm[n * 64 + sp], 1e-8f);
        float pn = ps_sm[sp] + c * cosp - c * cosm;
        pn_sm[sp] = pn;
        out_t[(size_t)n * ROW + 1 + ANa + 1 + Hh + sp] = pn;
    }
    out_t[(size_t)n * ROW + 18 + tid] = s_sm[tid];
    if (tid < 16) out_t[(size_t)n * ROW + 1 + tid] = probs_sm[tid];
    if (tid == 0) {
        out_t[(size_t)n * ROW + 0] = (float)a;
        out_t[(size_t)n * ROW + 17] = v_sm;
    }
    __syncthreads();
    // fused: softmax(pn) -> ps_buf, r = ps @ M -> r_out (for next step)
    if (tid == 0) {
        float m = pn_sm[0];
        for (int i = 1; i < 64; i++) m = fmaxf(m, pn_sm[i]);
        float sum = 0.f;
        for (int i = 0; i < 64; i++) { float e = expf(pn_sm[i] - m); ps_sm[i] = e; sum += e; }
        float inv = 1.f / sum;
        for (int i = 0; i < 64; i++) ps_sm[i] *= inv;
    }
    __syncthreads();
    if (tid < 64) ps_buf[n * 64 + tid] = ps_sm[tid];
    float acc = 0.f;
    for (int s = 0; s < 64; s++)
        acc += ps_sm[s] * X[(size_t)(s * Nn + n) * HGg + 2 + tid];
    r_out[n * 256 + tid] = acc;
}

__global__ void copy_last(float* __restrict__ out, int out_size)
{
    int idx = blockIdx.x * 256 + threadIdx.x;
    if (idx >= Nn * ROW) return;
    int dst = Tt * Nn * ROW + idx;
    if (dst < out_size) out[dst] = out[(Tt - 1) * Nn * ROW + idx];
}

// ---------------- orchestration ----------------
extern "C" void kernel_launch(void* const* d_in, const int* in_sizes, int n_in,
                              void* d_out, int out_size)
{
    const float* base    = (const float*)d_in[0];
    const float* inter   = (const float*)d_in[1];
    const float* hxs     = (const float*)d_in[2];
    const float* emb     = (const float*)d_in[3];
    const float* w_ih    = (const float*)d_in[4];
    const float* w_hh    = (const float*)d_in[5];
    const float* b_ih    = (const float*)d_in[6];
    const float* b_hh    = (const float*)d_in[7];
    const float* conv0_w = (const float*)d_in[8];
    const float* conv0_b = (const float*)d_in[9];
    const float* convs_w = (const float*)d_in[10];
    const float* convs_b = (const float*)d_in[11];
    const float* lin_w   = (const float*)d_in[12];
    const float* lin_b   = (const float*)d_in[13];
    const float* psi_w   = (const float*)d_in[14];
    const float* psi_b   = (const float*)d_in[15];
    const float* actor_w = (const float*)d_in[16];
    const float* actor_b = (const float*)d_in[17];
    const float* critic_w= (const float*)d_in[18];
    const float* critic_b= (const float*)d_in[19];
    const int*   subtasks= (const int*)d_in[20];
    const int*   actions = (const int*)d_in[21];
    float* out = (float*)d_out;

    float *GIvT, *GIall, *GH, *whhP, *Xt, *Xn, *W0t, *linT, *psiT, *p, *ps, *nMp, *nMm, *r, *G, *x0, *x1, *sb, *lp;
    cudaGetSymbolAddress((void**)&GIvT,  g_GIvT);
    cudaGetSymbolAddress((void**)&GIall, g_GIall);
    cudaGetSymbolAddress((void**)&GH,    g_GH);
    cudaGetSymbolAddress((void**)&whhP,  g_whhP);
    cudaGetSymbolAddress((void**)&Xt,    g_Xt);
    cudaGetSymbolAddress((void**)&Xn,    g_Xn);
    cudaGetSymbolAddress((void**)&W0t,   g_W0t);
    cudaGetSymbolAddress((void**)&linT,  g_linT);
    cudaGetSymbolAddress((void**)&psiT,  g_psiT);
    cudaGetSymbolAddress((void**)&p,     g_p);
    cudaGetSymbolAddress((void**)&ps,    g_ps);
    cudaGetSymbolAddress((void**)&nMp,   g_nMp);
    cudaGetSymbolAddress((void**)&nMm,   g_nMm);
    cudaGetSymbolAddress((void**)&r,     g_r);
    cudaGetSymbolAddress((void**)&G,     g_G);
    cudaGetSymbolAddress((void**)&x0,    g_x0);
    cudaGetSymbolAddress((void**)&x1,    g_x1);
    cudaGetSymbolAddress((void**)&sb,    g_s);
    cudaGetSymbolAddress((void**)&lp,    g_lp);

    // prologue
    transpose_w0 <<<2048, 256>>>(conv0_w, W0t);
    transpose_lin<<<16384, 256>>>(lin_w, linT);
    transpose_psi<<<4096, 256>>>(psi_w, psiT);
    pad_whh<<<(G3 * KP + 255) / 256, 256>>>(w_hh, whhP);
    zero_xt_pad<<<(Ss * (KP - HGg) * Nn + 255) / 256, 256>>>(Xt);
    // GIvT[j'][v] = sum_k w_ih[j',k] emb[v,k]
    sg<0><<<dim3(19, 1, 1), 256>>>(w_ih, 256, emb, 256, GIvT, G3, 32, 256, nullptr, 0);
    gather_gi<<<dim3(Ss, (G3 * 64 + 255) / 256), 256>>>(GIvT, subtasks, GIall);

    // GRU recurrence
    for (int s = 0; s < Ss; s++) {
        if (s > 0)
            sg<1><<<dim3(19, 1, 10), 256>>>(whhP, KP, Xt + (size_t)(s - 1) * XSTEP, 64,
                                            GH, G3, 64, KP, nullptr, 0);
        gru_gate<<<(HGg * Nn + 255) / 256, 256>>>(GIall, GH, b_ih, b_hh, Xt, s);
    }
    transpose_X<<<dim3(Ss, 13), 256>>>(Xt, Xn);

    norms_kernel<<<Nn * Ss, 128>>>(Xn, nMp, nMm);
    p_init_kernel<<<Nn, 128>>>(hxs, Xn, p);
    step_a<<<Nn, 256>>>(p, ps, r, Xn);

    // scan over T=32 steps
    for (int t = 0; t < Tt; t++) {
        sg<0><<<dim3(16, 1, 4), 256>>>(W0t, 256, r, 256, G, 2048, 64, 256, nullptr, 0);
        step_c<<<dim3(Nn, 4), 256>>>(G, base + (size_t)t * Nn * 512, conv0_b, x0);
        sg<0><<<dim3(32, 4, 1), 256>>>(x0, 256, convs_w, 256, x1,
                                       4096, 256, 256, convs_b, 1);
        sg<0><<<dim3(32, 4, 1), 256>>>(x1, 256, convs_w + 65536, 256, x0,
                                       4096, 256, 256, convs_b + 256, 1);
        sg<0><<<dim3(2, 1, 64), 256>>>(linT, 16384, x0, 16384, lp,
                                       256, 64, 16384, nullptr, 0);
        lin_reduce<<<Nn, 256>>>(lp, lin_b, sb);
        step_head<<<Nn, 256>>>(sb, ps, Xn, nMp, nMm, psiT, psi_b, actor_w, actor_b,
                               critic_w, critic_b, inter + (size_t)t * Nn * 11,
                               actions + t * Nn, r, out + (size_t)t * Nn * ROW);
    }
    copy_last<<<(Nn * ROW + 255) / 256, 256>>>(out, out_size);
}